// round 8
// baseline (speedup 1.0000x reference)
#include <cuda_runtime.h>
#include <math.h>
#include <float.h>

// Problem constants (fixed shapes from setup_inputs)
#define BQ   4
#define HTOT 32
#define HKV  8
#define GQ   4
#define DD   128
#define PP   128
#define SS   64
#define KP   16
#define NGROUP (BQ*HKV*GQ)   // 128
#define NEGV (-1000000000.0f)

// Scratch (no allocations allowed)
__device__ float g_qh[BQ*HKV*GQ*DD];
__device__ float g_kcur[BQ*HKV*DD];
__device__ float g_curscore[NGROUP];
__device__ float g_scores[NGROUP*PP*SS];      // 4 MB
__device__ float g_pagestats[NGROUP*PP];
__device__ int   g_sel[NGROUP*KP];
__device__ float g_m[NGROUP];
__device__ float g_invl[NGROUP];

__device__ __forceinline__ float sm_scale_f32() {
    // float32 rounding of 1/sqrt(128) (python float -> f32, as jnp does)
    return (float)0.08838834764831845;
}

// ---------------------------------------------------------------------------
// Kernel 0: RoPE(q), RoPE(k_cur), cur_score = qh . k_cur * sm_scale
// grid: 32 blocks (b*8+h), 128 threads (d)
// XLA-GPU-emulating arithmetic:
//   pf   = __nv_powf(10000, i/64)      (libdevice powf, what XLA GPU emits)
//   invf = 1.0f / pf                   (div.rn.f32)
//   ang  = pos * invf                  (f32 mul)
//   c,s  = __nv_cosf/__nv_sinf(ang)    (libdevice, XLA GPU lowering of cos/sin)
//   out  = x1*c - x2*s with UNFUSED f32 mul/sub (no FMA contraction)
// ---------------------------------------------------------------------------
__global__ void rope_kernel(const float* __restrict__ q,
                            const float* __restrict__ k,
                            const int*   __restrict__ timestep)
{
    int bh = blockIdx.x;            // b*8 + h
    int b  = bh >> 3;
    int h  = bh & 7;
    int d  = threadIdx.x;

    int ts = timestep ? timestep[0] : 8192;
    float pos = (float)(ts - 1);

    int i = d & 63;
    float x    = (float)i * 0.015625f;       // exact
    float pf   = powf(10000.0f, x);          // libdevice __nv_powf (precise path)
    float invf = __fdiv_rn(1.0f, pf);        // f32 IEEE division
    float ang  = __fmul_rn(pos, invf);
    float c  = cosf(ang);                    // libdevice __nv_cosf
    float sn = sinf(ang);                    // libdevice __nv_sinf

    const float* kb = k + bh * DD;
    float kx1 = kb[i], kx2 = kb[i + 64];
    float kval = (d < 64)
        ? __fsub_rn(__fmul_rn(kx1, c),  __fmul_rn(kx2, sn))
        : __fadd_rn(__fmul_rn(kx1, sn), __fmul_rn(kx2, c));
    g_kcur[bh * DD + d] = kval;

    __shared__ float red[128];
    for (int g = 0; g < GQ; g++) {
        const float* qb = q + ((b * HTOT) + h * GQ + g) * DD;
        float qx1 = qb[i], qx2 = qb[i + 64];
        float qval = (d < 64)
            ? __fsub_rn(__fmul_rn(qx1, c),  __fmul_rn(qx2, sn))
            : __fadd_rn(__fmul_rn(qx1, sn), __fmul_rn(qx2, c));
        g_qh[(bh * GQ + g) * DD + d] = qval;

        red[d] = qval * kval;
        __syncthreads();
        for (int off = 64; off; off >>= 1) {
            if (d < off) red[d] += red[d + off];
            __syncthreads();
        }
        if (d == 0) g_curscore[bh * GQ + g] = red[0] * sm_scale_f32();
        __syncthreads();
    }
}

// ---------------------------------------------------------------------------
// Kernel 1: full scores + per-page max.
//   kc[d] = f32(k_int) * sk  (one f32 rounding per element, materialized)
//   dot   = sequential fmaf over d = 0..127 ascending (single accumulator)
//   score = dot * sm_scale (separate f32 multiply)
// grid (P=128, HKV=8, B=4), 256 threads: thread -> (s = tid>>2, g = tid&3)
// ---------------------------------------------------------------------------
#define KROW 132   // padded row stride in floats (16B aligned, bank-safe)

__global__ __launch_bounds__(256)
void score_kernel(const int*   __restrict__ k_cache,
                  const float* __restrict__ kvscale,
                  const int*   __restrict__ lengths)
{
    int p = blockIdx.x;
    int h = blockIdx.y;
    int b = blockIdx.z;
    int tid  = threadIdx.x;
    int bh   = b * HKV + h;
    int gbase = bh * GQ;

    int len = lengths[b];
    if (len < 1) len = 1;

    if (p * SS >= len) {
        // fully masked page: fill scores with NEG, page stats NEG (no K load)
        int g = tid >> 6, s = tid & 63;   // 256 threads = 4*64 exactly
        g_scores[(((size_t)(gbase + g)) * PP + p) * SS + s] = NEGV;
        if (tid < GQ) g_pagestats[(gbase + tid) * PP + p] = NEGV;
        return;
    }

    __shared__ float kS[SS * KROW];
    __shared__ float qS[GQ * KROW];
    __shared__ float smax[8][4];

    float sk = kvscale[0];

    // Stage K tile: 64 tokens x 128 ints, convert to f32 * sk (rounded once).
    {
        const int4* kbase = (const int4*)(k_cache
            + (((size_t)(b * PP + p)) * SS) * (HKV * DD) + h * DD);
        // 2048 int4 vectors, 256 threads -> 8 each
        #pragma unroll
        for (int it = 0; it < 8; it++) {
            int idx = it * 256 + tid;       // 0..2047
            int s = idx >> 5;               // token
            int j = idx & 31;               // int4 within row
            int4 kv = kbase[(size_t)s * (HKV * DD / 4) + j];
            float* dst = &kS[s * KROW + j * 4];
            dst[0] = __fmul_rn((float)kv.x, sk);
            dst[1] = __fmul_rn((float)kv.y, sk);
            dst[2] = __fmul_rn((float)kv.z, sk);
            dst[3] = __fmul_rn((float)kv.w, sk);
        }
        // q: 4 groups x 128 floats = 512 items over 256 threads (2 passes)
        #pragma unroll
        for (int it = 0; it < 2; it++) {
            int idx = it * 256 + tid;       // 0..511
            int g = idx >> 7, d2 = idx & 127;
            qS[g * KROW + d2] = g_qh[(gbase + g) * DD + d2];
        }
    }
    __syncthreads();

    int s = tid >> 2;     // token 0..63
    int g = tid & 3;      // group 0..3

    // Sequential FMA chain over d ascending.
    const float4* kq = (const float4*)&kS[s * KROW];
    const float4* qq = (const float4*)&qS[g * KROW];
    float acc = 0.0f;
    #pragma unroll
    for (int j = 0; j < 32; j++) {
        float4 kv = kq[j];
        float4 qv = qq[j];
        acc = fmaf(qv.x, kv.x, acc);
        acc = fmaf(qv.y, kv.y, acc);
        acc = fmaf(qv.z, kv.z, acc);
        acc = fmaf(qv.w, kv.w, acc);
    }

    int pos = p * SS + s;
    float sc = (pos < len) ? __fmul_rn(acc, sm_scale_f32()) : NEGV;
    g_scores[(((size_t)(gbase + g)) * PP + p) * SS + s] = sc;

    // per-(page,g) max
    float gm = sc;
    #pragma unroll
    for (int off = 4; off < 32; off <<= 1)
        gm = fmaxf(gm, __shfl_xor_sync(0xffffffffu, gm, off));
    int w = tid >> 5, lane = tid & 31;
    if (lane < 4) smax[w][lane] = gm;
    __syncthreads();
    if (tid < 4) {
        float m = smax[0][tid];
        #pragma unroll
        for (int ww = 1; ww < 8; ww++) m = fmaxf(m, smax[ww][tid]);
        g_pagestats[(gbase + tid) * PP + p] = m;
    }
}

// ---------------------------------------------------------------------------
// Kernel 2: top-15 over pages [0,127) + fixed page 127.
// lax.top_k semantics: descending value, ties -> smaller index first.
// grid 128 blocks, 32 threads.
// ---------------------------------------------------------------------------
__global__ void topk_kernel(float* __restrict__ out_idx)
{
    int grp  = blockIdx.x;
    int lane = threadIdx.x;

    float vals[4];
    #pragma unroll
    for (int j = 0; j < 4; j++) {
        int idx = j * 32 + lane;
        vals[j] = (idx < PP - 1) ? g_pagestats[grp * PP + idx] : -FLT_MAX;
    }

    for (int kk = 0; kk < KP - 1; kk++) {
        float bv = -FLT_MAX; int bi = 0x7fffffff;
        #pragma unroll
        for (int j = 0; j < 4; j++) {
            int idx = j * 32 + lane;
            if (vals[j] > bv || (vals[j] == bv && idx < bi)) { bv = vals[j]; bi = idx; }
        }
        #pragma unroll
        for (int off = 16; off; off >>= 1) {
            float ov = __shfl_xor_sync(0xffffffffu, bv, off);
            int   oi = __shfl_xor_sync(0xffffffffu, bi, off);
            if (ov > bv || (ov == bv && oi < bi)) { bv = ov; bi = oi; }
        }
        if (lane == 0) {
            g_sel[grp * KP + kk]   = bi;
            out_idx[grp * KP + kk] = (float)bi;
        }
        int slot = bi >> 5, ol = bi & 31;
        if (lane == ol) {
            if (slot == 0) vals[0] = -FLT_MAX;
            else if (slot == 1) vals[1] = -FLT_MAX;
            else if (slot == 2) vals[2] = -FLT_MAX;
            else vals[3] = -FLT_MAX;
        }
    }
    if (lane == 0) {
        g_sel[grp * KP + KP - 1]   = PP - 1;
        out_idx[grp * KP + KP - 1] = (float)(PP - 1);
    }
}

// ---------------------------------------------------------------------------
// Kernel 3a: softmax stats per group; init out with current-token term.
// grid 128 blocks (group), 256 threads.
// ---------------------------------------------------------------------------
__global__ __launch_bounds__(256)
void softmax_kernel(const float* __restrict__ v,
                    float*       __restrict__ out)
{
    int grp = blockIdx.x;
    int b = grp >> 5;
    int h = (grp >> 2) & 7;
    int g = grp & 3;
    int tid = threadIdx.x;

    __shared__ float ssc[KP * SS];
    __shared__ float red[256];
    __shared__ int   selS[KP];

    if (tid < KP) selS[tid] = g_sel[grp * KP + tid];
    __syncthreads();

    for (int t = tid; t < KP * SS; t += 256) {
        int kk = t >> 6, s = t & 63;
        ssc[t] = g_scores[(((size_t)grp) * PP + selS[kk]) * SS + s];
    }
    __syncthreads();

    float cur = g_curscore[grp];
    float m = (tid == 0) ? cur : -FLT_MAX;
    for (int t = tid; t < KP * SS; t += 256) m = fmaxf(m, ssc[t]);
    red[tid] = m; __syncthreads();
    for (int off = 128; off; off >>= 1) {
        if (tid < off) red[tid] = fmaxf(red[tid], red[tid + off]);
        __syncthreads();
    }
    m = red[0];
    __syncthreads();

    float sum = (tid == 0) ? expf(cur - m) : 0.0f;
    for (int t = tid; t < KP * SS; t += 256) sum += expf(ssc[t] - m);
    red[tid] = sum; __syncthreads();
    for (int off = 128; off; off >>= 1) {
        if (tid < off) red[tid] += red[tid + off];
        __syncthreads();
    }
    float invl = 1.0f / red[0];

    if (tid == 0) { g_m[grp] = m; g_invl[grp] = invl; }

    if (tid < DD) {
        float pcur = expf(cur - m) * invl;
        out[((b * HTOT) + h * GQ + g) * DD + tid] =
            pcur * v[(b * HKV + h) * DD + tid];
    }
}

// ---------------------------------------------------------------------------
// Kernel 3b: weighted V accumulation, one block per (group, selected page).
// grid 2048 blocks, 128 threads (one per d).
// ---------------------------------------------------------------------------
__global__ __launch_bounds__(128)
void av_kernel(const int*   __restrict__ v_cache,
               const float* __restrict__ kvscale,
               float*       __restrict__ out)
{
    int blk = blockIdx.x;
    int grp = blk >> 4;
    int kk  = blk & 15;
    int b = grp >> 5;
    int h = (grp >> 2) & 7;
    int g = grp & 3;
    int tid = threadIdx.x;

    __shared__ float e[SS];
    __shared__ int anyflag;

    int page  = g_sel[grp * KP + kk];
    float m    = g_m[grp];
    float invl = g_invl[grp];

    if (tid == 0) anyflag = 0;
    __syncthreads();
    if (tid < SS) {
        float ev = expf(g_scores[(((size_t)grp) * PP + page) * SS + tid] - m) * invl;
        e[tid] = ev;
        if (ev > 0.0f) anyflag = 1;
    }
    __syncthreads();
    if (!anyflag) return;   // fully masked page (only possible for page 127)

    const int* vb = v_cache + (((size_t)(b * PP + page)) * SS) * (HKV * DD)
                            + h * DD + tid;
    float acc = 0.0f;
    #pragma unroll 8
    for (int s = 0; s < SS; s++) {
        acc += e[s] * (float)vb[(size_t)s * (HKV * DD)];
    }
    atomicAdd(&out[((b * HTOT) + h * GQ + g) * DD + tid], acc * kvscale[1]);
}

// ---------------------------------------------------------------------------
extern "C" void kernel_launch(void* const* d_in, const int* in_sizes, int n_in,
                              void* d_out, int out_size)
{
    const float* q        = (const float*)d_in[0];
    const float* k        = (const float*)d_in[1];
    const float* v        = (const float*)d_in[2];
    const float* kvscale  = (const float*)d_in[3];
    const int*   k_cache  = (const int*)  d_in[4];
    const int*   v_cache  = (const int*)  d_in[5];
    const int*   lengths  = (const int*)  d_in[6];
    const int*   timestep = (n_in >= 8) ? (const int*)d_in[7] : nullptr;

    float* out = (float*)d_out;                 // [B,H,D] = 16384 floats
    float* out_idx = out + BQ * HTOT * DD;      // [B,H,KP] = 2048 (as float)

    rope_kernel<<<BQ * HKV, 128>>>(q, k, timestep);
    score_kernel<<<dim3(PP, HKV, BQ), 256>>>(k_cache, kvscale, lengths);
    topk_kernel<<<NGROUP, 32>>>(out_idx);
    softmax_kernel<<<NGROUP, 256>>>(v, out);
    av_kernel<<<NGROUP * KP, 128>>>(v_cache, kvscale, out);

    (void)in_sizes; (void)out_size;
}

// round 9
// speedup vs baseline: 1.3466x; 1.3466x over previous
#include <cuda_runtime.h>
#include <math.h>
#include <float.h>

// Problem constants (fixed shapes from setup_inputs)
#define BQ   4
#define HTOT 32
#define HKV  8
#define GQ   4
#define DD   128
#define PP   128
#define SS   64
#define KP   16
#define NGROUP (BQ*HKV*GQ)   // 128
#define NEGV (-1000000000.0f)

// Scratch (no allocations allowed)
__device__ float g_qh[BQ*HKV*GQ*DD];
__device__ float g_kcur[BQ*HKV*DD];
__device__ float g_curscore[NGROUP];
__device__ float g_scores[NGROUP*PP*SS];      // 4 MB
__device__ float g_pagestats[NGROUP*PP];
__device__ int   g_sel[NGROUP*KP];
__device__ float g_m[NGROUP];
__device__ float g_invl[NGROUP];

__device__ __forceinline__ float sm_scale_f32() {
    // float32 rounding of 1/sqrt(128) (python float -> f32, as jnp does)
    return (float)0.08838834764831845;
}

// ---------------------------------------------------------------------------
// Kernel 0: RoPE(q), RoPE(k_cur), cur_score = qh . k_cur * sm_scale
// grid: 32 blocks (b*8+h), 128 threads (d)
// XLA-GPU-emulating arithmetic:
//   pf   = __nv_powf(10000, i/64)      (libdevice powf, what XLA GPU emits)
//   invf = 1.0f / pf                   (div.rn.f32)
//   ang  = pos * invf                  (f32 mul)
//   c,s  = __nv_cosf/__nv_sinf(ang)    (libdevice, XLA GPU lowering of cos/sin)
//   out  = x1*c - x2*s with UNFUSED f32 mul/sub (no FMA contraction)
// ---------------------------------------------------------------------------
__global__ void rope_kernel(const float* __restrict__ q,
                            const float* __restrict__ k,
                            const int*   __restrict__ timestep)
{
    int bh = blockIdx.x;            // b*8 + h
    int b  = bh >> 3;
    int h  = bh & 7;
    int d  = threadIdx.x;

    int ts = timestep ? timestep[0] : 8192;
    float pos = (float)(ts - 1);

    int i = d & 63;
    float x    = (float)i * 0.015625f;       // exact
    float pf   = powf(10000.0f, x);          // libdevice __nv_powf (precise path)
    float invf = __fdiv_rn(1.0f, pf);        // f32 IEEE division
    float ang  = __fmul_rn(pos, invf);
    float c  = cosf(ang);                    // libdevice __nv_cosf
    float sn = sinf(ang);                    // libdevice __nv_sinf

    const float* kb = k + bh * DD;
    float kx1 = kb[i], kx2 = kb[i + 64];
    float kval = (d < 64)
        ? __fsub_rn(__fmul_rn(kx1, c),  __fmul_rn(kx2, sn))
        : __fadd_rn(__fmul_rn(kx1, sn), __fmul_rn(kx2, c));
    g_kcur[bh * DD + d] = kval;

    __shared__ float red[128];
    for (int g = 0; g < GQ; g++) {
        const float* qb = q + ((b * HTOT) + h * GQ + g) * DD;
        float qx1 = qb[i], qx2 = qb[i + 64];
        float qval = (d < 64)
            ? __fsub_rn(__fmul_rn(qx1, c),  __fmul_rn(qx2, sn))
            : __fadd_rn(__fmul_rn(qx1, sn), __fmul_rn(qx2, c));
        g_qh[(bh * GQ + g) * DD + d] = qval;

        red[d] = qval * kval;
        __syncthreads();
        for (int off = 64; off; off >>= 1) {
            if (d < off) red[d] += red[d + off];
            __syncthreads();
        }
        if (d == 0) g_curscore[bh * GQ + g] = red[0] * sm_scale_f32();
        __syncthreads();
    }
}

// ---------------------------------------------------------------------------
// Kernel 1: full scores + per-page max.
//   kc[d] = f32(k_int) * sk  (one f32 rounding per element, materialized)
//   dot   = sequential fmaf over d = 0..127 ascending (single accumulator)
//   score = dot * sm_scale (separate f32 multiply)
// grid (P=128, HKV=8, B=4), 256 threads: thread -> (s = tid>>2, g = tid&3)
// ---------------------------------------------------------------------------
#define KROW 132   // padded row stride in floats (16B aligned, bank-safe)

__global__ __launch_bounds__(256)
void score_kernel(const int*   __restrict__ k_cache,
                  const float* __restrict__ kvscale,
                  const int*   __restrict__ lengths)
{
    int p = blockIdx.x;
    int h = blockIdx.y;
    int b = blockIdx.z;
    int tid  = threadIdx.x;
    int bh   = b * HKV + h;
    int gbase = bh * GQ;

    int len = lengths[b];
    if (len < 1) len = 1;

    if (p * SS >= len) {
        // fully masked page: fill scores with NEG, page stats NEG (no K load)
        int g = tid >> 6, s = tid & 63;   // 256 threads = 4*64 exactly
        g_scores[(((size_t)(gbase + g)) * PP + p) * SS + s] = NEGV;
        if (tid < GQ) g_pagestats[(gbase + tid) * PP + p] = NEGV;
        return;
    }

    __shared__ float kS[SS * KROW];
    __shared__ float qS[GQ * KROW];
    __shared__ float smax[8][4];

    float sk = kvscale[0];

    // Stage K tile: 64 tokens x 128 ints, convert to f32 * sk (rounded once).
    {
        const int4* kbase = (const int4*)(k_cache
            + (((size_t)(b * PP + p)) * SS) * (HKV * DD) + h * DD);
        // 2048 int4 vectors, 256 threads -> 8 each
        #pragma unroll
        for (int it = 0; it < 8; it++) {
            int idx = it * 256 + tid;       // 0..2047
            int s = idx >> 5;               // token
            int j = idx & 31;               // int4 within row
            int4 kv = kbase[(size_t)s * (HKV * DD / 4) + j];
            float* dst = &kS[s * KROW + j * 4];
            dst[0] = __fmul_rn((float)kv.x, sk);
            dst[1] = __fmul_rn((float)kv.y, sk);
            dst[2] = __fmul_rn((float)kv.z, sk);
            dst[3] = __fmul_rn((float)kv.w, sk);
        }
        // q: 4 groups x 128 floats = 512 items over 256 threads (2 passes)
        #pragma unroll
        for (int it = 0; it < 2; it++) {
            int idx = it * 256 + tid;       // 0..511
            int g = idx >> 7, d2 = idx & 127;
            qS[g * KROW + d2] = g_qh[(gbase + g) * DD + d2];
        }
    }
    __syncthreads();

    int s = tid >> 2;     // token 0..63
    int g = tid & 3;      // group 0..3

    // Sequential FMA chain over d ascending.
    const float4* kq = (const float4*)&kS[s * KROW];
    const float4* qq = (const float4*)&qS[g * KROW];
    float acc = 0.0f;
    #pragma unroll
    for (int j = 0; j < 32; j++) {
        float4 kv = kq[j];
        float4 qv = qq[j];
        acc = fmaf(qv.x, kv.x, acc);
        acc = fmaf(qv.y, kv.y, acc);
        acc = fmaf(qv.z, kv.z, acc);
        acc = fmaf(qv.w, kv.w, acc);
    }

    int pos = p * SS + s;
    float sc = (pos < len) ? __fmul_rn(acc, sm_scale_f32()) : NEGV;
    g_scores[(((size_t)(gbase + g)) * PP + p) * SS + s] = sc;

    // per-(page,g) max
    float gm = sc;
    #pragma unroll
    for (int off = 4; off < 32; off <<= 1)
        gm = fmaxf(gm, __shfl_xor_sync(0xffffffffu, gm, off));
    int w = tid >> 5, lane = tid & 31;
    if (lane < 4) smax[w][lane] = gm;
    __syncthreads();
    if (tid < 4) {
        float m = smax[0][tid];
        #pragma unroll
        for (int ww = 1; ww < 8; ww++) m = fmaxf(m, smax[ww][tid]);
        g_pagestats[(gbase + tid) * PP + p] = m;
    }
}

// ---------------------------------------------------------------------------
// Kernel 2: top-15 over pages [0,127) + fixed page 127.
// lax.top_k semantics: descending value, ties -> smaller index first.
// grid 128 blocks, 32 threads.
// ---------------------------------------------------------------------------
__global__ void topk_kernel(float* __restrict__ out_idx)
{
    int grp  = blockIdx.x;
    int lane = threadIdx.x;

    float vals[4];
    #pragma unroll
    for (int j = 0; j < 4; j++) {
        int idx = j * 32 + lane;
        vals[j] = (idx < PP - 1) ? g_pagestats[grp * PP + idx] : -FLT_MAX;
    }

    for (int kk = 0; kk < KP - 1; kk++) {
        float bv = -FLT_MAX; int bi = 0x7fffffff;
        #pragma unroll
        for (int j = 0; j < 4; j++) {
            int idx = j * 32 + lane;
            if (vals[j] > bv || (vals[j] == bv && idx < bi)) { bv = vals[j]; bi = idx; }
        }
        #pragma unroll
        for (int off = 16; off; off >>= 1) {
            float ov = __shfl_xor_sync(0xffffffffu, bv, off);
            int   oi = __shfl_xor_sync(0xffffffffu, bi, off);
            if (ov > bv || (ov == bv && oi < bi)) { bv = ov; bi = oi; }
        }
        if (lane == 0) {
            g_sel[grp * KP + kk]   = bi;
            out_idx[grp * KP + kk] = (float)bi;
        }
        int slot = bi >> 5, ol = bi & 31;
        if (lane == ol) {
            if (slot == 0) vals[0] = -FLT_MAX;
            else if (slot == 1) vals[1] = -FLT_MAX;
            else if (slot == 2) vals[2] = -FLT_MAX;
            else vals[3] = -FLT_MAX;
        }
    }
    if (lane == 0) {
        g_sel[grp * KP + KP - 1]   = PP - 1;
        out_idx[grp * KP + KP - 1] = (float)(PP - 1);
    }
}

// ---------------------------------------------------------------------------
// Kernel 3a: softmax stats per group; init out with current-token term.
// grid 128 blocks (group), 256 threads.
// ---------------------------------------------------------------------------
__global__ __launch_bounds__(256)
void softmax_kernel(const float* __restrict__ v,
                    float*       __restrict__ out)
{
    int grp = blockIdx.x;
    int b = grp >> 5;
    int h = (grp >> 2) & 7;
    int g = grp & 3;
    int tid = threadIdx.x;

    __shared__ float ssc[KP * SS];
    __shared__ float red[256];
    __shared__ int   selS[KP];

    if (tid < KP) selS[tid] = g_sel[grp * KP + tid];
    __syncthreads();

    for (int t = tid; t < KP * SS; t += 256) {
        int kk = t >> 6, s = t & 63;
        ssc[t] = g_scores[(((size_t)grp) * PP + selS[kk]) * SS + s];
    }
    __syncthreads();

    float cur = g_curscore[grp];
    float m = (tid == 0) ? cur : -FLT_MAX;
    for (int t = tid; t < KP * SS; t += 256) m = fmaxf(m, ssc[t]);
    red[tid] = m; __syncthreads();
    for (int off = 128; off; off >>= 1) {
        if (tid < off) red[tid] = fmaxf(red[tid], red[tid + off]);
        __syncthreads();
    }
    m = red[0];
    __syncthreads();

    float sum = (tid == 0) ? expf(cur - m) : 0.0f;
    for (int t = tid; t < KP * SS; t += 256) sum += expf(ssc[t] - m);
    red[tid] = sum; __syncthreads();
    for (int off = 128; off; off >>= 1) {
        if (tid < off) red[tid] += red[tid + off];
        __syncthreads();
    }
    float invl = 1.0f / red[0];

    if (tid == 0) { g_m[grp] = m; g_invl[grp] = invl; }

    if (tid < DD) {
        float pcur = expf(cur - m) * invl;
        out[((b * HTOT) + h * GQ + g) * DD + tid] =
            pcur * v[(b * HKV + h) * DD + tid];
    }
}

// ---------------------------------------------------------------------------
// Kernel 3b: weighted V accumulation, one block per (group, selected page).
// grid 2048 blocks, 128 threads (one per d).
// ---------------------------------------------------------------------------
__global__ __launch_bounds__(128)
void av_kernel(const int*   __restrict__ v_cache,
               const float* __restrict__ kvscale,
               float*       __restrict__ out)
{
    int blk = blockIdx.x;
    int grp = blk >> 4;
    int kk  = blk & 15;
    int b = grp >> 5;
    int h = (grp >> 2) & 7;
    int g = grp & 3;
    int tid = threadIdx.x;

    __shared__ float e[SS];
    __shared__ int anyflag;

    int page  = g_sel[grp * KP + kk];
    float m    = g_m[grp];
    float invl = g_invl[grp];

    if (tid == 0) anyflag = 0;
    __syncthreads();
    if (tid < SS) {
        float ev = expf(g_scores[(((size_t)grp) * PP + page) * SS + tid] - m) * invl;
        e[tid] = ev;
        if (ev > 0.0f) anyflag = 1;
    }
    __syncthreads();
    if (!anyflag) return;   // fully masked page (only possible for page 127)

    const int* vb = v_cache + (((size_t)(b * PP + page)) * SS) * (HKV * DD)
                            + h * DD + tid;
    float acc = 0.0f;
    #pragma unroll 8
    for (int s = 0; s < SS; s++) {
        acc += e[s] * (float)vb[(size_t)s * (HKV * DD)];
    }
    atomicAdd(&out[((b * HTOT) + h * GQ + g) * DD + tid], acc * kvscale[1]);
}

// ---------------------------------------------------------------------------
extern "C" void kernel_launch(void* const* d_in, const int* in_sizes, int n_in,
                              void* d_out, int out_size)
{
    const float* q        = (const float*)d_in[0];
    const float* k        = (const float*)d_in[1];
    const float* v        = (const float*)d_in[2];
    const float* kvscale  = (const float*)d_in[3];
    const int*   k_cache  = (const int*)  d_in[4];
    const int*   v_cache  = (const int*)  d_in[5];
    const int*   lengths  = (const int*)  d_in[6];
    const int*   timestep = (n_in >= 8) ? (const int*)d_in[7] : nullptr;

    float* out = (float*)d_out;                 // [B,H,D] = 16384 floats
    float* out_idx = out + BQ * HTOT * DD;      // [B,H,KP] = 2048 (as float)

    rope_kernel<<<BQ * HKV, 128>>>(q, k, timestep);
    score_kernel<<<dim3(PP, HKV, BQ), 256>>>(k_cache, kvscale, lengths);
    topk_kernel<<<NGROUP, 32>>>(out_idx);
    softmax_kernel<<<NGROUP, 256>>>(v, out);
    av_kernel<<<NGROUP * KP, 128>>>(v_cache, kvscale, out);

    (void)in_sizes; (void)out_size;
}

// round 10
// speedup vs baseline: 1.4452x; 1.0732x over previous
#include <cuda_runtime.h>
#include <math.h>
#include <float.h>

// Problem constants (fixed shapes from setup_inputs)
#define BQ   4
#define HTOT 32
#define HKV  8
#define GQ   4
#define DD   128
#define PP   128
#define SS   64
#define KP   16
#define NGROUP (BQ*HKV*GQ)   // 128
#define NEGV (-1000000000.0f)

// Scratch (no allocations allowed)
__device__ float g_qh[BQ*HKV*GQ*DD];
__device__ float g_curscore[NGROUP];
__device__ float g_scores[NGROUP*PP*SS];      // 4 MB
__device__ float g_pagestats[NGROUP*PP];
__device__ int   g_sel[NGROUP*KP];
__device__ float g_m[NGROUP];
__device__ float g_invl[NGROUP];

__device__ __forceinline__ float sm_scale_f32() {
    return (float)0.08838834764831845;   // f32(1/sqrt(128))
}

// ---------------------------------------------------------------------------
// Kernel 0: RoPE(q), RoPE(k_cur), cur_score = qh . k_cur * sm_scale
// CORRECTNESS-CRITICAL arithmetic (validated R9): libdevice powf/cosf/sinf,
// f32 division, unfused mul/sub. Do not change.
// ---------------------------------------------------------------------------
__global__ void rope_kernel(const float* __restrict__ q,
                            const float* __restrict__ k,
                            const int*   __restrict__ timestep)
{
    int bh = blockIdx.x;            // b*8 + h
    int b  = bh >> 3;
    int h  = bh & 7;
    int d  = threadIdx.x;

    int ts = timestep ? timestep[0] : 8192;
    float pos = (float)(ts - 1);

    int i = d & 63;
    float x    = (float)i * 0.015625f;       // exact
    float pf   = powf(10000.0f, x);          // libdevice __nv_powf (precise)
    float invf = __fdiv_rn(1.0f, pf);        // f32 IEEE division
    float ang  = __fmul_rn(pos, invf);
    float c  = cosf(ang);                    // libdevice __nv_cosf
    float sn = sinf(ang);                    // libdevice __nv_sinf

    const float* kb = k + bh * DD;
    float kx1 = kb[i], kx2 = kb[i + 64];
    float kval = (d < 64)
        ? __fsub_rn(__fmul_rn(kx1, c),  __fmul_rn(kx2, sn))
        : __fadd_rn(__fmul_rn(kx1, sn), __fmul_rn(kx2, c));

    __shared__ float red[128];
    for (int g = 0; g < GQ; g++) {
        const float* qb = q + ((b * HTOT) + h * GQ + g) * DD;
        float qx1 = qb[i], qx2 = qb[i + 64];
        float qval = (d < 64)
            ? __fsub_rn(__fmul_rn(qx1, c),  __fmul_rn(qx2, sn))
            : __fadd_rn(__fmul_rn(qx1, sn), __fmul_rn(qx2, c));
        g_qh[(bh * GQ + g) * DD + d] = qval;

        red[d] = qval * kval;
        __syncthreads();
        for (int off = 64; off; off >>= 1) {
            if (d < off) red[d] += red[d + off];
            __syncthreads();
        }
        if (d == 0) g_curscore[bh * GQ + g] = red[0] * sm_scale_f32();
        __syncthreads();
    }
}

// ---------------------------------------------------------------------------
// Kernel 1: full scores + per-page max.
// CORRECTNESS-CRITICAL: kc[d]=f32(int)*sk rounded once; sequential fmaf chain
// over d ascending; separate *sm_scale. Do not change arithmetic.
// grid (P=128, HKV=8, B=4), 256 threads: thread -> (s = tid>>2, g = tid&3)
// ---------------------------------------------------------------------------
#define KROW 132   // padded row stride in floats (16B aligned, bank-safe)

__global__ __launch_bounds__(256)
void score_kernel(const int*   __restrict__ k_cache,
                  const float* __restrict__ kvscale,
                  const int*   __restrict__ lengths)
{
    int p = blockIdx.x;
    int h = blockIdx.y;
    int b = blockIdx.z;
    int tid  = threadIdx.x;
    int bh   = b * HKV + h;
    int gbase = bh * GQ;

    int len = lengths[b];
    if (len < 1) len = 1;

    if (p * SS >= len) {
        // fully masked page: fill scores with NEG, page stats NEG (no K load)
        int g = tid >> 6, s = tid & 63;   // 256 threads = 4*64 exactly
        g_scores[(((size_t)(gbase + g)) * PP + p) * SS + s] = NEGV;
        if (tid < GQ) g_pagestats[(gbase + tid) * PP + p] = NEGV;
        return;
    }

    __shared__ float kS[SS * KROW];
    __shared__ float qS[GQ * KROW];
    __shared__ float smax[8][4];

    float sk = kvscale[0];

    // Stage K tile: 64 tokens x 128 ints, convert to f32 * sk (rounded once).
    {
        const int4* kbase = (const int4*)(k_cache
            + (((size_t)(b * PP + p)) * SS) * (HKV * DD) + h * DD);
        #pragma unroll
        for (int it = 0; it < 8; it++) {
            int idx = it * 256 + tid;       // 0..2047
            int s = idx >> 5;               // token
            int j = idx & 31;               // int4 within row
            int4 kv = kbase[(size_t)s * (HKV * DD / 4) + j];
            float* dst = &kS[s * KROW + j * 4];
            dst[0] = __fmul_rn((float)kv.x, sk);
            dst[1] = __fmul_rn((float)kv.y, sk);
            dst[2] = __fmul_rn((float)kv.z, sk);
            dst[3] = __fmul_rn((float)kv.w, sk);
        }
        #pragma unroll
        for (int it = 0; it < 2; it++) {
            int idx = it * 256 + tid;       // 0..511
            int g = idx >> 7, d2 = idx & 127;
            qS[g * KROW + d2] = g_qh[(gbase + g) * DD + d2];
        }
    }
    __syncthreads();

    int s = tid >> 2;     // token 0..63
    int g = tid & 3;      // group 0..3

    // Sequential FMA chain over d ascending.
    const float4* kq = (const float4*)&kS[s * KROW];
    const float4* qq = (const float4*)&qS[g * KROW];
    float acc = 0.0f;
    #pragma unroll
    for (int j = 0; j < 32; j++) {
        float4 kv = kq[j];
        float4 qv = qq[j];
        acc = fmaf(qv.x, kv.x, acc);
        acc = fmaf(qv.y, kv.y, acc);
        acc = fmaf(qv.z, kv.z, acc);
        acc = fmaf(qv.w, kv.w, acc);
    }

    int pos = p * SS + s;
    float sc = (pos < len) ? __fmul_rn(acc, sm_scale_f32()) : NEGV;
    g_scores[(((size_t)(gbase + g)) * PP + p) * SS + s] = sc;

    // per-(page,g) max
    float gm = sc;
    #pragma unroll
    for (int off = 4; off < 32; off <<= 1)
        gm = fmaxf(gm, __shfl_xor_sync(0xffffffffu, gm, off));
    int w = tid >> 5, lane = tid & 31;
    if (lane < 4) smax[w][lane] = gm;
    __syncthreads();
    if (tid < 4) {
        float m = smax[0][tid];
        #pragma unroll
        for (int ww = 1; ww < 8; ww++) m = fmaxf(m, smax[ww][tid]);
        g_pagestats[(gbase + tid) * PP + p] = m;
    }
}

// ---------------------------------------------------------------------------
// Kernel 2 (fused): top-k (warp 0) + softmax stats + out init.
// grid 128 blocks (group), 256 threads.
// ---------------------------------------------------------------------------
__global__ __launch_bounds__(256)
void topk_softmax_kernel(const float* __restrict__ v,
                         float*       __restrict__ out,
                         float*       __restrict__ out_idx)
{
    int grp = blockIdx.x;
    int b = grp >> 5;
    int h = (grp >> 2) & 7;
    int g = grp & 3;
    int tid  = threadIdx.x;
    int lane = tid & 31;
    int w    = tid >> 5;

    __shared__ int   selS[KP];
    __shared__ float ssc[KP * SS];
    __shared__ float wredm[8];
    __shared__ float wreds[8];
    __shared__ float bcast[2];

    // ---- top-k on warp 0 (lax.top_k semantics: desc value, smaller idx first)
    if (w == 0) {
        float vals[4];
        #pragma unroll
        for (int j = 0; j < 4; j++) {
            int idx = j * 32 + lane;
            vals[j] = (idx < PP - 1) ? g_pagestats[grp * PP + idx] : -FLT_MAX;
        }
        for (int kk = 0; kk < KP - 1; kk++) {
            float bv = -FLT_MAX; int bi = 0x7fffffff;
            #pragma unroll
            for (int j = 0; j < 4; j++) {
                int idx = j * 32 + lane;
                if (vals[j] > bv || (vals[j] == bv && idx < bi)) { bv = vals[j]; bi = idx; }
            }
            #pragma unroll
            for (int off = 16; off; off >>= 1) {
                float ov = __shfl_xor_sync(0xffffffffu, bv, off);
                int   oi = __shfl_xor_sync(0xffffffffu, bi, off);
                if (ov > bv || (ov == bv && oi < bi)) { bv = ov; bi = oi; }
            }
            if (lane == 0) {
                selS[kk] = bi;
                g_sel[grp * KP + kk]   = bi;
                out_idx[grp * KP + kk] = (float)bi;
            }
            int slot = bi >> 5, ol = bi & 31;
            if (lane == ol) {
                if (slot == 0) vals[0] = -FLT_MAX;
                else if (slot == 1) vals[1] = -FLT_MAX;
                else if (slot == 2) vals[2] = -FLT_MAX;
                else vals[3] = -FLT_MAX;
            }
        }
        if (lane == 0) {
            selS[KP - 1] = PP - 1;
            g_sel[grp * KP + KP - 1]   = PP - 1;
            out_idx[grp * KP + KP - 1] = (float)(PP - 1);
        }
    }
    __syncthreads();

    // ---- gather selected scores
    #pragma unroll
    for (int it = 0; it < 4; it++) {
        int t = it * 256 + tid;             // 0..1023
        int kk = t >> 6, s = t & 63;
        ssc[t] = g_scores[(((size_t)grp) * PP + selS[kk]) * SS + s];
    }
    __syncthreads();

    float cur = g_curscore[grp];

    // ---- max (warp shuffles, 2 levels)
    float m = (tid == 0) ? cur : -FLT_MAX;
    #pragma unroll
    for (int it = 0; it < 4; it++) m = fmaxf(m, ssc[it * 256 + tid]);
    #pragma unroll
    for (int off = 16; off; off >>= 1)
        m = fmaxf(m, __shfl_xor_sync(0xffffffffu, m, off));
    if (lane == 0) wredm[w] = m;
    __syncthreads();
    if (tid < 32) {
        float x = (lane < 8) ? wredm[lane] : -FLT_MAX;
        #pragma unroll
        for (int off = 4; off; off >>= 1)
            x = fmaxf(x, __shfl_xor_sync(0xffffffffu, x, off));
        if (lane == 0) bcast[0] = x;
    }
    __syncthreads();
    m = bcast[0];

    // ---- sum (warp shuffles, 2 levels)
    float sum = (tid == 0) ? expf(cur - m) : 0.0f;
    #pragma unroll
    for (int it = 0; it < 4; it++) sum += expf(ssc[it * 256 + tid] - m);
    #pragma unroll
    for (int off = 16; off; off >>= 1)
        sum += __shfl_xor_sync(0xffffffffu, sum, off);
    if (lane == 0) wreds[w] = sum;
    __syncthreads();
    if (tid < 32) {
        float x = (lane < 8) ? wreds[lane] : 0.0f;
        #pragma unroll
        for (int off = 4; off; off >>= 1)
            x += __shfl_xor_sync(0xffffffffu, x, off);
        if (lane == 0) bcast[1] = x;
    }
    __syncthreads();
    float invl = 1.0f / bcast[1];

    if (tid == 0) { g_m[grp] = m; g_invl[grp] = invl; }

    if (tid < DD) {
        float pcur = expf(cur - m) * invl;
        out[((b * HTOT) + h * GQ + g) * DD + tid] =
            pcur * v[(b * HKV + h) * DD + tid];
    }
}

// ---------------------------------------------------------------------------
// Kernel 3: weighted V accumulation, one block per (group, selected page).
// grid 2048 blocks, 256 threads: (half = tid>>7 handles 32 tokens, d = tid&127)
// ---------------------------------------------------------------------------
__global__ __launch_bounds__(256)
void av_kernel(const int*   __restrict__ v_cache,
               const float* __restrict__ kvscale,
               float*       __restrict__ out)
{
    int blk = blockIdx.x;
    int grp = blk >> 4;
    int kk  = blk & 15;
    int b = grp >> 5;
    int h = (grp >> 2) & 7;
    int g = grp & 3;
    int tid = threadIdx.x;

    __shared__ float e[SS];
    __shared__ float part[DD];
    __shared__ int anyflag;

    int page  = g_sel[grp * KP + kk];
    float m    = g_m[grp];
    float invl = g_invl[grp];

    if (tid == 0) anyflag = 0;
    __syncthreads();
    if (tid < SS) {
        float ev = expf(g_scores[(((size_t)grp) * PP + page) * SS + tid] - m) * invl;
        e[tid] = ev;
        if (ev > 0.0f) anyflag = 1;
    }
    __syncthreads();
    if (!anyflag) return;   // fully masked page (only possible for page 127)

    int half = tid >> 7;    // 0/1: tokens [0,32) / [32,64)
    int d    = tid & 127;
    const int* vb = v_cache + (((size_t)(b * PP + page)) * SS + half * 32) * (HKV * DD)
                            + h * DD + d;
    float acc = 0.0f;
    #pragma unroll 8
    for (int s = 0; s < 32; s++) {
        acc += e[half * 32 + s] * (float)vb[(size_t)s * (HKV * DD)];
    }
    if (half) part[d] = acc;
    __syncthreads();
    if (!half) {
        atomicAdd(&out[((b * HTOT) + h * GQ + g) * DD + d],
                  (acc + part[d]) * kvscale[1]);
    }
}

// ---------------------------------------------------------------------------
extern "C" void kernel_launch(void* const* d_in, const int* in_sizes, int n_in,
                              void* d_out, int out_size)
{
    const float* q        = (const float*)d_in[0];
    const float* k        = (const float*)d_in[1];
    const float* v        = (const float*)d_in[2];
    const float* kvscale  = (const float*)d_in[3];
    const int*   k_cache  = (const int*)  d_in[4];
    const int*   v_cache  = (const int*)  d_in[5];
    const int*   lengths  = (const int*)  d_in[6];
    const int*   timestep = (n_in >= 8) ? (const int*)d_in[7] : nullptr;

    float* out = (float*)d_out;                 // [B,H,D] = 16384 floats
    float* out_idx = out + BQ * HTOT * DD;      // [B,H,KP] = 2048 (as float)

    rope_kernel<<<BQ * HKV, 128>>>(q, k, timestep);
    score_kernel<<<dim3(PP, HKV, BQ), 256>>>(k_cache, kvscale, lengths);
    topk_softmax_kernel<<<NGROUP, 256>>>(v, out, out_idx);
    av_kernel<<<NGROUP * KP, 256>>>(v_cache, kvscale, out);

    (void)in_sizes; (void)out_size;
}